// round 15
// baseline (speedup 1.0000x reference)
#include <cuda_runtime.h>
#include <cuda_bf16.h>

#define IW 1280
#define IH 720
#define IB 32
#define WPC 8                    // warps per CTA
#define HCH 5                    // 128-px chunks per half-row job
#define RING 512                 // floats per warp ring (4 chunk slots)
#define NJOBS (IB * IH * 2)      // 46080 half-row jobs
#define NCTAS (152 * 6)          // persistent grid: 6 CTAs per SM

__device__ int g_ctr;

__global__ void reset_ctr_kernel() { g_ctr = 0; }

__global__ __launch_bounds__(WPC * 32, 6) void warp_disp_pers(
    const float* __restrict__ img,
    const float* __restrict__ disp,
    float* __restrict__ out)
{
    __shared__ float ring[WPC][RING];

    const int w    = threadIdx.x >> 5;
    const int lane = threadIdx.x & 31;
    const int l4   = lane * 4;
    float* rg = ring[w];

    const float4 z4 = make_float4(0.f, 0.f, 0.f, 0.f);
    const float  Ax = (float)IW / (float)(IW - 1);

    for (;;) {
        // ---- grab next half-row job ----
        int j;
        if (lane == 0) j = atomicAdd(&g_ctr, 1);
        j = __shfl_sync(0xffffffffu, j, 0);
        if (j >= NJOBS) break;

        const int rowi = j >> 1;               // = b*IH + y
        const int half = j & 1;
        const int xb0  = half * (HCH * 128);   // 0 or 640
        const int y    = rowi % IH;
        const int b    = rowi / IH;

        // ---- vertical terms (uniform per job) ----
        float iy  = fmaf((float)y, (float)IH / (float)(IH - 1), -0.5f);
        float y0f = floorf(iy);
        float wy1 = iy - y0f;
        float wy0 = 1.0f - wy1;
        int   y0  = (int)y0f;
        int   y1  = y0 + 1;
        bool  vy0 = (unsigned)y0 < (unsigned)IH;
        bool  vy1 = (unsigned)y1 < (unsigned)IH;

        const float* imgb = img + (size_t)b * (IH * IW);
        const float* r0p  = imgb + (vy0 ? y0 : 0) * IW;
        const float* r1p  = imgb + (vy1 ? y1 : 0) * IW;
        const float* dsp  = disp + (size_t)rowi * IW;
        float*       op   = out  + (size_t)rowi * IW;

        // ---- prologue: slot 0 = left context (zeros or 68-float halo) ----
        float4 hm = z4;
        if (half && lane >= 15) {
            int gx = xb0 - 128 + l4;           // 512+l4, in-bounds
            float4 p0 = vy0 ? *reinterpret_cast<const float4*>(r0p + gx) : z4;
            float4 p1 = vy1 ? *reinterpret_cast<const float4*>(r1p + gx) : z4;
            hm.x = fmaf(wy0, p0.x, wy1 * p1.x);
            hm.y = fmaf(wy0, p0.y, wy1 * p1.y);
            hm.z = fmaf(wy0, p0.z, wy1 * p1.z);
            hm.w = fmaf(wy0, p0.w, wy1 * p1.w);
        }
        *reinterpret_cast<float4*>(rg + l4) = hm;

        // rel-chunk 0 -> slot 1 ; rel-chunk 1 -> pipeline reg B
        float4 a0 = vy0 ? *reinterpret_cast<const float4*>(r0p + xb0 + l4) : z4;
        float4 a1 = vy1 ? *reinterpret_cast<const float4*>(r1p + xb0 + l4) : z4;
        float4 b0 = vy0 ? *reinterpret_cast<const float4*>(r0p + xb0 + 128 + l4) : z4;
        float4 b1 = vy1 ? *reinterpret_cast<const float4*>(r1p + xb0 + 128 + l4) : z4;
        {
            float4 h;
            h.x = fmaf(wy0, a0.x, wy1 * a1.x);
            h.y = fmaf(wy0, a0.y, wy1 * a1.y);
            h.z = fmaf(wy0, a0.z, wy1 * a1.z);
            h.w = fmaf(wy0, a0.w, wy1 * a1.w);
            *reinterpret_cast<float4*>(rg + 128 + l4) = h;
        }
        __syncwarp();

        // ---- main loop: iter s loads rel-chunk s+2, stores s+1, gathers s ----
#pragma unroll
        for (int s = 0; s < HCH; s++) {
            float4 A0 = z4, A1 = z4;
            if (s < HCH - 2) {
                int gx = xb0 + (s + 2) * 128 + l4;
                if (vy0) A0 = *reinterpret_cast<const float4*>(r0p + gx);
                if (vy1) A1 = *reinterpret_cast<const float4*>(r1p + gx);
            } else if (s == HCH - 2) {         // rel-chunk 5: lane 0, half 0 only
                if (!half && lane == 0) {
                    if (vy0) A0 = *reinterpret_cast<const float4*>(r0p + 640);
                    if (vy1) A1 = *reinterpret_cast<const float4*>(r1p + 640);
                }
            }
            float4 d4 = *reinterpret_cast<const float4*>(dsp + xb0 + s * 128 + l4);

            float4 h;
            h.x = fmaf(wy0, b0.x, wy1 * b1.x);
            h.y = fmaf(wy0, b0.y, wy1 * b1.y);
            h.z = fmaf(wy0, b0.z, wy1 * b1.z);
            h.w = fmaf(wy0, b0.w, wy1 * b1.w);
            *reinterpret_cast<float4*>(rg + ((s + 2) & 3) * 128 + l4) = h;
            __syncwarp();

            const int xb = xb0 + s * 128 + l4;
            float dv[4] = {d4.x, d4.y, d4.z, d4.w};
            float res[4];
#pragma unroll
            for (int i = 0; i < 4; i++) {
                float u   = (float)(xb + i) - dv[i];
                float ix  = fmaf(u, Ax, -0.5f);
                float x0f = floorf(ix);
                float wx1 = ix - x0f;
                float wx0 = 1.0f - wx1;
                int   xr  = (int)x0f - xb0 + 128;   // in [63, 768]
                float v0 = rg[xr & (RING - 1)];
                float v1 = rg[(xr + 1) & (RING - 1)];
                res[i] = fmaf(v1, wx1, v0 * wx0);
            }
            *reinterpret_cast<float4*>(op + xb0 + s * 128 + l4) =
                make_float4(res[0], res[1], res[2], res[3]);
            // no trailing syncwarp needed: next store hits slot (s+3)&3,
            // disjoint from this gather's slots {s,s+1,s+2}&3.

            b0 = A0; b1 = A1;
        }
    }
}

extern "C" void kernel_launch(void* const* d_in, const int* in_sizes, int n_in,
                              void* d_out, int out_size)
{
    const float* right_img = (const float*)d_in[0];
    const float* disp      = (const float*)d_in[1];
    float*       out       = (float*)d_out;

    reset_ctr_kernel<<<1, 1>>>();
    warp_disp_pers<<<NCTAS, WPC * 32>>>(right_img, disp, out);
}

// round 16
// speedup vs baseline: 1.0723x; 1.0723x over previous
#include <cuda_runtime.h>
#include <cuda_bf16.h>

#define IW 1280
#define IH 720
#define IB 32
#define WPC 4                    // warps per CTA (small CTA -> fine wave tail)
#define NCH 10                   // 128-px chunks per row
#define RING 512                 // floats per warp ring (4 chunk slots)

// slot of chunk c = ((c+1)&3)*128 ; h[x] lives at ring[(x+128)&511]

__global__ __launch_bounds__(WPC * 32) void warp_disp_ring4(
    const float* __restrict__ img,
    const float* __restrict__ disp,
    float* __restrict__ out)
{
    __shared__ float ring[WPC][RING];

    const int w    = threadIdx.x >> 5;
    const int lane = threadIdx.x & 31;
    const int l4   = lane * 4;
    const int rowi = blockIdx.x * WPC + w;     // = b*IH + y
    const int y    = rowi % IH;
    const int b    = rowi / IH;
    float* rg = ring[w];

    // ---- vertical terms (uniform per warp): iy = y*H/(H-1) - 0.5 ----
    float iy  = fmaf((float)y, (float)IH / (float)(IH - 1), -0.5f);
    float y0f = floorf(iy);
    float wy1 = iy - y0f;
    float wy0 = 1.0f - wy1;
    int   y0  = (int)y0f;
    int   y1  = y0 + 1;
    bool  vy0 = (unsigned)y0 < (unsigned)IH;
    bool  vy1 = (unsigned)y1 < (unsigned)IH;

    const float* imgb = img + (size_t)b * (IH * IW);
    const float* r0p  = imgb + (vy0 ? y0 : 0) * IW;
    const float* r1p  = imgb + (vy1 ? y1 : 0) * IW;
    const float* dsp  = disp + (size_t)rowi * IW;
    float*       op   = out  + (size_t)rowi * IW;

    const float4 z4 = make_float4(0.f, 0.f, 0.f, 0.f);
    const float  Ax = (float)IW / (float)(IW - 1);

    // ---- prologue ----
    // chunk -1 = zeros (slot 0)
    *reinterpret_cast<float4*>(rg + l4) = z4;
    // chunk 0 loads
    float4 a0 = vy0 ? *reinterpret_cast<const float4*>(r0p + l4) : z4;
    float4 a1 = vy1 ? *reinterpret_cast<const float4*>(r1p + l4) : z4;
    // chunk 1 loads (pipeline register B)
    float4 b0 = vy0 ? *reinterpret_cast<const float4*>(r0p + 128 + l4) : z4;
    float4 b1 = vy1 ? *reinterpret_cast<const float4*>(r1p + 128 + l4) : z4;
    // store chunk 0 (slot 1)
    {
        float4 h;
        h.x = fmaf(wy0, a0.x, wy1 * a1.x);
        h.y = fmaf(wy0, a0.y, wy1 * a1.y);
        h.z = fmaf(wy0, a0.z, wy1 * a1.z);
        h.w = fmaf(wy0, a0.w, wy1 * a1.w);
        *reinterpret_cast<float4*>(rg + 128 + l4) = h;
    }
    __syncwarp();

    // ---- main loop: iteration s loads chunk s+2, stores chunk s+1, gathers s ----
#pragma unroll
    for (int s = 0; s < NCH; s++) {
        const int c = s + 2;
        float4 A0 = z4, A1 = z4;
        if (c < NCH) {
            if (vy0) A0 = *reinterpret_cast<const float4*>(r0p + c * 128 + l4);
            if (vy1) A1 = *reinterpret_cast<const float4*>(r1p + c * 128 + l4);
        }
        float4 d4 = *reinterpret_cast<const float4*>(dsp + s * 128 + l4);

        // store chunk s+1 from B at slot ((s+2)&3)
        float4 h;
        h.x = fmaf(wy0, b0.x, wy1 * b1.x);
        h.y = fmaf(wy0, b0.y, wy1 * b1.y);
        h.z = fmaf(wy0, b0.z, wy1 * b1.z);
        h.w = fmaf(wy0, b0.w, wy1 * b1.w);
        *reinterpret_cast<float4*>(rg + ((s + 2) & 3) * 128 + l4) = h;
        __syncwarp();

        // gather chunk s: taps span [s*128-65, s*128+128] -> chunks s-1, s, s+1
        const int xb = s * 128 + l4;
        float dv[4] = {d4.x, d4.y, d4.z, d4.w};
        float res[4];
#pragma unroll
        for (int i = 0; i < 4; i++) {
            float u   = (float)(xb + i) - dv[i];
            float ix  = fmaf(u, Ax, -0.5f);
            float x0f = floorf(ix);
            float wx1 = ix - x0f;
            float wx0 = 1.0f - wx1;
            int   x0  = (int)x0f;               // >= xb-65 >= -65
            float v0 = rg[(x0 + 128) & (RING - 1)];
            float v1 = rg[(x0 + 129) & (RING - 1)];
            res[i] = fmaf(v1, wx1, v0 * wx0);
        }
        *reinterpret_cast<float4*>(op + s * 128 + l4) =
            make_float4(res[0], res[1], res[2], res[3]);
        // next iteration's store targets slot (s+3)&3, disjoint from
        // this gather's slots {s,s+1,s+2}&3 -> no trailing sync needed.

        b0 = A0; b1 = A1;
    }
}

extern "C" void kernel_launch(void* const* d_in, const int* in_sizes, int n_in,
                              void* d_out, int out_size)
{
    const float* right_img = (const float*)d_in[0];
    const float* disp      = (const float*)d_in[1];
    float*       out       = (float*)d_out;

    const int blocks = IB * IH / WPC;           // 5760 CTAs, 4 row-warps each
    warp_disp_ring4<<<blocks, WPC * 32>>>(right_img, disp, out);
}

// round 17
// speedup vs baseline: 1.3315x; 1.2417x over previous
#include <cuda_runtime.h>
#include <cuda_bf16.h>

#define IW 1280
#define IH 720
#define IB 32
#define WPC 8                    // warps per CTA (proven optimum)
#define NCH 10                   // 128-px chunks per row
#define RING 1024                // 8 chunk slots per warp (4 KB)

// slot of chunk c = ((c+1)&7)*128 ; h[x] lives at ring[(x+128)&1023]

__global__ __launch_bounds__(WPC * 32) void warp_disp_ring8(
    const float* __restrict__ img,
    const float* __restrict__ disp,
    float* __restrict__ out)
{
    __shared__ float ring[WPC][RING];

    const int w    = threadIdx.x >> 5;
    const int lane = threadIdx.x & 31;
    const int l4   = lane * 4;
    const int rowi = blockIdx.x * WPC + w;     // = b*IH + y
    const int y    = rowi % IH;
    const int b    = rowi / IH;
    float* rg = ring[w];

    // ---- vertical terms (uniform per warp): iy = y*H/(H-1) - 0.5 ----
    float iy  = fmaf((float)y, (float)IH / (float)(IH - 1), -0.5f);
    float y0f = floorf(iy);
    float wy1 = iy - y0f;
    float wy0 = 1.0f - wy1;
    int   y0  = (int)y0f;
    int   y1  = y0 + 1;
    bool  vy0 = (unsigned)y0 < (unsigned)IH;
    bool  vy1 = (unsigned)y1 < (unsigned)IH;

    const float* imgb = img + (size_t)b * (IH * IW);
    const float* r0p  = imgb + (vy0 ? y0 : 0) * IW;
    const float* r1p  = imgb + (vy1 ? y1 : 0) * IW;
    const float* dsp  = disp + (size_t)rowi * IW;
    float*       op   = out  + (size_t)rowi * IW;

    const float4 z4 = make_float4(0.f, 0.f, 0.f, 0.f);
    const float  Ax = (float)IW / (float)(IW - 1);

    // ---- prologue ----
    // chunk -1 = zeros (slot 0)
    *reinterpret_cast<float4*>(rg + l4) = z4;
    // chunk 0: load, lerp, store (slot 1)
    {
        float4 a0 = vy0 ? *reinterpret_cast<const float4*>(r0p + l4) : z4;
        float4 a1 = vy1 ? *reinterpret_cast<const float4*>(r1p + l4) : z4;
        float4 h;
        h.x = fmaf(wy0, a0.x, wy1 * a1.x);
        h.y = fmaf(wy0, a0.y, wy1 * a1.y);
        h.z = fmaf(wy0, a0.z, wy1 * a1.z);
        h.w = fmaf(wy0, a0.w, wy1 * a1.w);
        *reinterpret_cast<float4*>(rg + 128 + l4) = h;
    }
    // register queue: B1 = chunk 1, B2 = chunk 2
    float4 p0 = vy0 ? *reinterpret_cast<const float4*>(r0p + 128 + l4) : z4;
    float4 p1 = vy1 ? *reinterpret_cast<const float4*>(r1p + 128 + l4) : z4;
    float4 q0 = vy0 ? *reinterpret_cast<const float4*>(r0p + 256 + l4) : z4;
    float4 q1 = vy1 ? *reinterpret_cast<const float4*>(r1p + 256 + l4) : z4;
    __syncwarp();

    // ---- main loop: iter s loads chunk s+3, stores chunk s+1 (from B1),
    //      gathers chunk s.  LDG -> STS distance = 2 iterations. ----
#pragma unroll
    for (int s = 0; s < NCH; s++) {
        const int c = s + 3;
        float4 C0 = z4, C1 = z4;
        if (c < NCH) {
            if (vy0) C0 = *reinterpret_cast<const float4*>(r0p + c * 128 + l4);
            if (vy1) C1 = *reinterpret_cast<const float4*>(r1p + c * 128 + l4);
        }
        float4 d4 = *reinterpret_cast<const float4*>(dsp + s * 128 + l4);

        // store chunk s+1 from B1 at slot ((s+2)&7)
        float4 h;
        h.x = fmaf(wy0, p0.x, wy1 * p1.x);
        h.y = fmaf(wy0, p0.y, wy1 * p1.y);
        h.z = fmaf(wy0, p0.z, wy1 * p1.z);
        h.w = fmaf(wy0, p0.w, wy1 * p1.w);
        *reinterpret_cast<float4*>(rg + ((s + 2) & 7) * 128 + l4) = h;
        __syncwarp();

        // gather chunk s: taps span [s*128-65, s*128+128] -> chunks s-1,s,s+1
        const int xb = s * 128 + l4;
        float dv[4] = {d4.x, d4.y, d4.z, d4.w};
        float res[4];
#pragma unroll
        for (int i = 0; i < 4; i++) {
            float u   = (float)(xb + i) - dv[i];
            float ix  = fmaf(u, Ax, -0.5f);
            float x0f = floorf(ix);
            float wx1 = ix - x0f;
            float wx0 = 1.0f - wx1;
            int   x0  = (int)x0f;               // >= xb-65 >= -65
            float v0 = rg[(x0 + 128) & (RING - 1)];
            float v1 = rg[(x0 + 129) & (RING - 1)];
            res[i] = fmaf(v1, wx1, v0 * wx0);
        }
        *reinterpret_cast<float4*>(op + s * 128 + l4) =
            make_float4(res[0], res[1], res[2], res[3]);
        // next stores hit slots (s+3)&7, (s+4)&7 — disjoint from this
        // gather's slots {s, s+1, s+2}&7; reuse only 8 chunks later.

        p0 = q0; p1 = q1;                       // advance queue
        q0 = C0; q1 = C1;
    }
}

extern "C" void kernel_launch(void* const* d_in, const int* in_sizes, int n_in,
                              void* d_out, int out_size)
{
    const float* right_img = (const float*)d_in[0];
    const float* disp      = (const float*)d_in[1];
    float*       out       = (float*)d_out;

    const int blocks = IB * IH / WPC;           // 2880 CTAs, 8 row-warps each
    warp_disp_ring8<<<blocks, WPC * 32>>>(right_img, disp, out);
}